// round 13
// baseline (speedup 1.0000x reference)
#include <cuda_runtime.h>
#include <cuda_bf16.h>

#define B_ 4
#define N_ 512
#define D_ 128
#define H_ 128

typedef unsigned long long ull;
#define ABSMASK2 0x7fffffff7fffffffULL

// ---- packed f32x2 helpers -------------------------------------------------
__device__ __forceinline__ void fma2(ull &a, ull x, ull w) {
    asm("fma.rn.f32x2 %0, %1, %2, %0;" : "+l"(a) : "l"(x), "l"(w));
}
__device__ __forceinline__ ull add2(ull a, ull b) {
    ull r; asm("add.rn.f32x2 %0, %1, %2;" : "=l"(r) : "l"(a), "l"(b)); return r;
}
__device__ __forceinline__ ull pack2(float lo, float hi) {
    ull r; asm("mov.b64 %0, {%1, %2};" : "=l"(r) : "f"(lo), "f"(hi)); return r;
}
__device__ __forceinline__ void unpack2(ull v, float &lo, float &hi) {
    asm("mov.b64 {%0, %1}, %2;" : "=f"(lo), "=f"(hi) : "l"(v));
}
__device__ __forceinline__ float hadd2(ull v) { float lo, hi; unpack2(v, lo, hi); return lo + hi; }

// ---- scratch --------------------------------------------------------------
__device__ float gA[B_ * N_ * H_];
__device__ float gC[B_ * N_ * H_];
__device__ float gWA[B_ * N_];       // sum_h W2c[h]*A[row][h]
__device__ float gWC[B_ * N_];       // sum_h W2c[h]*C[row][h]
__device__ float gDiag[B_ * N_];

// ---------------------------------------------------------------------------
// Precompute (proven round-4 core + WA/WC/diag epilogue): 8 rows/block,
// 256 threads = h(128) x d-half(2), grid 256. Distance-2 weight prefetch.
// ---------------------------------------------------------------------------
#define RW 8

__global__ __launch_bounds__(256) void precompute_kernel(
    const float* __restrict__ X,
    const float* __restrict__ W1c, const float* __restrict__ b1c,
    const float* __restrict__ W1s, const float* __restrict__ b1s,
    const float* __restrict__ W2s, const float* __restrict__ b2s,
    const float* __restrict__ W2c)
{
    const int tid  = threadIdx.x;
    const int h    = tid & 127;
    const int half = tid >> 7;
    const int rowBase = blockIdx.x * RW;

    __shared__ float xs[RW][D_];
    __shared__ float redA[RW][H_];
    __shared__ float redC[RW][H_];
    __shared__ float redS[RW][H_];
    __shared__ float red4d[4][RW];
    __shared__ float red4a[4][RW];
    __shared__ float red4c[4][RW];

    {
        const float4* src = (const float4*)(X + (size_t)rowBase * D_);
        float4* dst = (float4*)&xs[0][0];
        for (int t = tid; t < RW * D_ / 4; t += 256) dst[t] = src[t];
    }
    __syncthreads();

    ull accA[RW], accC[RW], accS[RW];
#pragma unroll
    for (int r = 0; r < RW; r++) { accA[r] = 0ull; accC[r] = 0ull; accS[r] = 0ull; }

    const int dBase = half * 64;
    const float* pA = W1c + (size_t)dBase * H_ + h;
    const float* pC = W1c + (size_t)(dBase + D_) * H_ + h;
    const float* pS = W1s + (size_t)dBase * H_ + h;

    float wb[3][12];
#pragma unroll
    for (int p = 0; p < 2; p++) {
#pragma unroll
        for (int q = 0; q < 4; q++) {
            wb[p][q]     = pA[(p * 4 + q) * H_];
            wb[p][4 + q] = pC[(p * 4 + q) * H_];
            wb[p][8 + q] = pS[(p * 4 + q) * H_];
        }
    }

#pragma unroll
    for (int cc = 0; cc < 16; cc++) {
        const int cur = cc % 3;
        if (cc < 14) {
            const int nb  = (cc + 2) % 3;
            const int off = (cc + 2) * 4;
#pragma unroll
            for (int q = 0; q < 4; q++) {
                wb[nb][q]     = pA[(off + q) * H_];
                wb[nb][4 + q] = pC[(off + q) * H_];
                wb[nb][8 + q] = pS[(off + q) * H_];
            }
        }
        const ull wa01 = pack2(wb[cur][0], wb[cur][1]);
        const ull wa23 = pack2(wb[cur][2], wb[cur][3]);
        const ull wc01 = pack2(wb[cur][4], wb[cur][5]);
        const ull wc23 = pack2(wb[cur][6], wb[cur][7]);
        const ull ws01 = pack2(wb[cur][8], wb[cur][9]);
        const ull ws23 = pack2(wb[cur][10], wb[cur][11]);
        const int d0 = dBase + cc * 4;
#pragma unroll
        for (int r = 0; r < RW; r++) {
            const ulonglong2 xv = *(const ulonglong2*)&xs[r][d0];
            fma2(accA[r], xv.x, wa01); fma2(accA[r], xv.y, wa23);
            fma2(accC[r], xv.x, wc01); fma2(accC[r], xv.y, wc23);
            fma2(accS[r], xv.x, ws01); fma2(accS[r], xv.y, ws23);
        }
    }

    if (half == 1) {
#pragma unroll
        for (int r = 0; r < RW; r++) {
            redA[r][h] = hadd2(accA[r]);
            redC[r][h] = hadd2(accC[r]);
            redS[r][h] = hadd2(accS[r]);
        }
    }
    __syncthreads();

    if (half == 0) {
        const float bc  = b1c[h];
        const float bs  = b1s[h];
        const float w2s = W2s[h];
        const float w2c = W2c[h];
#pragma unroll
        for (int r = 0; r < RW; r++) {
            const float a = hadd2(accA[r]) + redA[r][h];
            const float c = hadd2(accC[r]) + redC[r][h] + bc;
            gA[(size_t)(rowBase + r) * H_ + h] = a;
            gC[(size_t)(rowBase + r) * H_ + h] = c;
            float t  = fmaxf(hadd2(accS[r]) + redS[r][h] + bs, 0.f) * w2s;
            float ta = a * w2c;
            float tc = c * w2c;
#pragma unroll
            for (int off = 16; off > 0; off >>= 1) {
                t  += __shfl_down_sync(0xffffffffu, t,  off);
                ta += __shfl_down_sync(0xffffffffu, ta, off);
                tc += __shfl_down_sync(0xffffffffu, tc, off);
            }
            if ((h & 31) == 0) {
                red4d[h >> 5][r] = t;
                red4a[h >> 5][r] = ta;
                red4c[h >> 5][r] = tc;
            }
        }
    }
    __syncthreads();
    if (tid < RW) {
        const float sd = red4d[0][tid] + red4d[1][tid] + red4d[2][tid] + red4d[3][tid] + b2s[0];
        gDiag[rowBase + tid] = 1.f / (1.f + __expf(-sd));
        gWA[rowBase + tid] = red4a[0][tid] + red4a[1][tid] + red4a[2][tid] + red4a[3][tid];
        gWC[rowBase + tid] = red4c[0][tid] + red4c[1][tid] + red4c[2][tid] + red4c[3][tid];
    }
}

// ---------------------------------------------------------------------------
// Pair kernel v13: 64x64 tile, 1024 threads (32 warps = 16 row-warps x 2
// h-halves). Each warp: 4x2 micro over its 64 h-values (abs-trick math,
// warp-broadcast A rows). Half-1 spills one float/cell to smem; half-0
// combines + sigmoid; all warps store. 8 warps/SMSP hides LDS latency.
// ---------------------------------------------------------------------------
#define PSTRIDE 132
#define SMEM_PAIR_BYTES ((2 * 64 * PSTRIDE + 128 + 64 + 64 + 16) * 4)

__global__ __launch_bounds__(1024) void pair_kernel(
    const float* __restrict__ W2c, const float* __restrict__ b2c,
    float* __restrict__ out)
{
    extern __shared__ float sm[];
    float* As = sm;                             // [64][132]
    float* Cs = sm + 64 * PSTRIDE;              // [64][132]
    float* ws = sm + 2 * 64 * PSTRIDE;          // [128]
    float* wa = ws + 128;                       // [64]
    float* wc = wa + 64;                        // [64]

    int t = blockIdx.x, ti = 0;
    while (t >= 8 - ti) { t -= 8 - ti; ti++; }
    const int tj = ti + t;
    const int b  = blockIdx.y;

    const int tid = threadIdx.x;
    const int i0 = ti * 64, j0 = tj * 64;

    {
        const float4* ga4 = (const float4*)(gA + ((size_t)b * N_ + i0) * H_);
        const float4* gc4 = (const float4*)(gC + ((size_t)b * N_ + j0) * H_);
#pragma unroll
        for (int k = 0; k < 2; k++) {
            const int e = k * 1024 + tid;
            const int r = e >> 5, c = e & 31;
            ((float4*)&As[r * PSTRIDE])[c] = ga4[r * 32 + c];
            ((float4*)&Cs[r * PSTRIDE])[c] = gc4[r * 32 + c];
        }
        if (tid < 128)      ws[tid] = W2c[tid];
        else if (tid < 192) wa[tid - 128] = gWA[b * N_ + i0 + (tid - 128)];
        else if (tid < 256) wc[tid - 192] = gWC[b * N_ + j0 + (tid - 192)];
    }
    __syncthreads();

    const int wid = tid >> 5;
    const int ty  = wid & 15;    // row warp -> rows ty+16k (broadcast loads)
    const int hh  = wid >> 4;    // h-half
    const int tx  = tid & 31;    // lane -> cols tx+32m (conflict-free)
    const int hBase = hh * 64;

    const float* aBase = &As[ty * PSTRIDE + hBase];
    const float* cBase = &Cs[tx * PSTRIDE + hBase];

    ull acc[4][2];
#pragma unroll
    for (int k = 0; k < 4; k++) { acc[k][0] = 0ull; acc[k][1] = 0ull; }

#pragma unroll 4
    for (int s = 0; s < 16; s++) {
        const int h4 = s * 4;
        ulonglong2 av[4], cv[2];
#pragma unroll
        for (int k = 0; k < 4; k++)
            av[k] = *(const ulonglong2*)(aBase + (16 * k) * PSTRIDE + h4);
#pragma unroll
        for (int m = 0; m < 2; m++)
            cv[m] = *(const ulonglong2*)(cBase + (32 * m) * PSTRIDE + h4);
        const ulonglong2 wv = *(const ulonglong2*)&ws[hBase + h4];

#pragma unroll
        for (int k = 0; k < 4; k++) {
#pragma unroll
            for (int m = 0; m < 2; m++) {
                const ull x0 = add2(av[k].x, cv[m].x) & ABSMASK2;
                const ull x1 = add2(av[k].y, cv[m].y) & ABSMASK2;
                fma2(acc[k][m], x0, wv.x);
                fma2(acc[k][m], x1, wv.y);
            }
        }
    }

    // half-1 spills partial |.|-sums to smem (aliased onto As; reads done)
    __syncthreads();
    float* redP = As;                          // [64][65]
    if (hh == 1) {
#pragma unroll
        for (int k = 0; k < 4; k++)
#pragma unroll
            for (int m = 0; m < 2; m++)
                redP[(ty + 16 * k) * 65 + (tx + 32 * m)] = hadd2(acc[k][m]);
    }
    __syncthreads();

    float* St = Cs;                            // [64][65] (aliased onto Cs)
#define ST(i, j) St[(i) * 65 + (j)]

    if (hh == 0) {
        const float bb = b2c[0];
        if (ti != tj) {
#pragma unroll
            for (int k = 0; k < 4; k++) {
                const int i = ty + 16 * k;
                const float wai = wa[i];
#pragma unroll
                for (int m = 0; m < 2; m++) {
                    const int j = tx + 32 * m;
                    const float part = hadd2(acc[k][m]) + redP[i * 65 + j];
                    const float pre  = fmaf(0.5f, part, 0.5f * (wai + wc[j]) + bb);
                    ST(i, j) = 1.f / (1.f + __expf(-pre));
                }
            }
        } else {
            const int gi0 = b * N_ + i0;
#pragma unroll
            for (int k = 0; k < 4; k++) {
                const int i = ty + 16 * k;
                const float wai = wa[i];
#pragma unroll
                for (int m = 0; m < 2; m++) {
                    const int j = tx + 32 * m;
                    if (i < j) {
                        const float part = hadd2(acc[k][m]) + redP[i * 65 + j];
                        const float pre  = fmaf(0.5f, part, 0.5f * (wai + wc[j]) + bb);
                        const float sv = 1.f / (1.f + __expf(-pre));
                        ST(i, j) = sv;
                        ST(j, i) = sv;
                    } else if (i == j) {
                        ST(i, i) = gDiag[gi0 + i];
                    }
                }
            }
        }
    }
    __syncthreads();

    // stores: 1024 threads, 1 direct f4 (+1 transposed if off-diag) each
    {
        const int r = tid >> 4, c = (tid & 15) * 4;
        float4 v = make_float4(ST(r, c), ST(r, c + 1), ST(r, c + 2), ST(r, c + 3));
        *(float4*)&out[((size_t)b * N_ + i0 + r) * N_ + j0 + c] = v;
        if (ti != tj) {
            float4 vt = make_float4(ST(c, r), ST(c + 1, r), ST(c + 2, r), ST(c + 3, r));
            *(float4*)&out[((size_t)b * N_ + j0 + r) * N_ + i0 + c] = vt;
        }
    }
#undef ST
}

// ---------------------------------------------------------------------------
extern "C" void kernel_launch(void* const* d_in, const int* in_sizes, int n_in,
                              void* d_out, int out_size)
{
    const float* X   = (const float*)d_in[0];
    const float* W1c = (const float*)d_in[1];
    const float* b1c = (const float*)d_in[2];
    const float* W2c = (const float*)d_in[3];
    const float* b2c = (const float*)d_in[4];
    const float* W1s = (const float*)d_in[5];
    const float* b1s = (const float*)d_in[6];
    const float* W2s = (const float*)d_in[7];
    const float* b2s = (const float*)d_in[8];
    float* out = (float*)d_out;

    static bool attrSet = false;
    if (!attrSet) {
        cudaFuncSetAttribute(pair_kernel,
                             cudaFuncAttributeMaxDynamicSharedMemorySize,
                             SMEM_PAIR_BYTES);
        attrSet = true;
    }

    precompute_kernel<<<(B_ * N_) / RW, 256>>>(X, W1c, b1c, W1s, b1s, W2s, b2s, W2c);

    dim3 grid(36, B_);   // triangular 64x64 tiles x batch
    pair_kernel<<<grid, 1024, SMEM_PAIR_BYTES>>>(W2c, b2c, out);
}